// round 4
// baseline (speedup 1.0000x reference)
#include <cuda_runtime.h>
#include <cstdint>

// LSTM: B=64, T=4096, H=128, gates i,f,g,o; Linear(H->1) on h_T.
// 64 clusters x 2 CTAs (128 CTAs, 1/SM). Each CTA owns hidden [rank*64, rank*64+64).
// Thread map: q = tid&3 (gate), jloc = tid>>2. 256 gate rows/CTA, weights fully
// register-resident as f32x2 pairs split into local/remote column halves.
// Per step: local-half dot overlaps the peer DSMEM flight; remote h arrives via
// ONE cp.async.bulk (256B) + mbarrier complete_tx; cta-scope acquire on the wait;
// MUFU.TANH activations; one __syncthreads per step.

#define B_ 64
#define T_ 4096
#define H_ 128
#define NT 256

__device__ __forceinline__ uint32_t smem_u32(const void* p) {
    uint32_t a;
    asm("{ .reg .u64 t; cvta.to.shared.u64 t, %1; cvt.u32.u64 %0, t; }" : "=r"(a) : "l"(p));
    return a;
}
__device__ __forceinline__ uint32_t ctarank() {
    uint32_t r; asm("mov.u32 %0, %%cluster_ctarank;" : "=r"(r)); return r;
}
__device__ __forceinline__ uint32_t mapa_u32(uint32_t a, uint32_t rk) {
    uint32_t r; asm("mapa.shared::cluster.u32 %0, %1, %2;" : "=r"(r) : "r"(a), "r"(rk)); return r;
}
__device__ __forceinline__ float tanh_fast(float x) {
    float y; asm("tanh.approx.f32 %0, %1;" : "=f"(y) : "f"(x)); return y;
}

// 32 packed FMAs (64 floats) of one column-half: W[32] f32x2 pairs vs 16 LDS.128 of h.
#define DOT_HALF(Wp, HP)                                                              \
    _Pragma("unroll")                                                                 \
    for (int i_ = 0; i_ < 8; i_++) {                                                  \
        ulonglong2 h2_ = (HP)[2*i_], h3_ = (HP)[2*i_ + 1];                            \
        asm("fma.rn.f32x2 %0, %1, %2, %0;" : "+l"(a0) : "l"((Wp)[4*i_    ]), "l"(h2_.x)); \
        asm("fma.rn.f32x2 %0, %1, %2, %0;" : "+l"(a1) : "l"((Wp)[4*i_ + 1]), "l"(h2_.y)); \
        asm("fma.rn.f32x2 %0, %1, %2, %0;" : "+l"(a2) : "l"((Wp)[4*i_ + 2]), "l"(h3_.x)); \
        asm("fma.rn.f32x2 %0, %1, %2, %0;" : "+l"(a3) : "l"((Wp)[4*i_ + 3]), "l"(h3_.y)); \
    }

// cta-scope acquire: async-proxy data delivered with complete_tx into LOCAL smem
// (same visibility contract as TMA-delivered data).
#define MBAR_WAIT(addr, par)                                                          \
    asm volatile(                                                                     \
        "{\n\t"                                                                       \
        ".reg .pred P1;\n\t"                                                          \
        "WL_%=:\n\t"                                                                  \
        "mbarrier.try_wait.parity.acquire.cta.shared::cta.b64 P1, [%0], %1, 0x989680;\n\t" \
        "@P1 bra.uni WD_%=;\n\t"                                                      \
        "bra.uni WL_%=;\n\t"                                                          \
        "WD_%=:\n\t"                                                                  \
        "}" :: "r"(addr), "r"(par) : "memory")

__global__ void __launch_bounds__(NT, 1) __cluster_dims__(2, 1, 1)
lstm_kernel(const float* __restrict__ data, const float* __restrict__ h0,
            const float* __restrict__ c0,   const float* __restrict__ W_ih,
            const float* __restrict__ W_hh, const float* __restrict__ b_ih,
            const float* __restrict__ b_hh, const float* __restrict__ W_out,
            const float* __restrict__ b_out, float* __restrict__ out)
{
    __shared__ __align__(16) float hbuf[2][H_];   // double-buffered full hidden state
    __shared__ __align__(16) float xs[T_];        // whole input sequence for this batch
    __shared__ __align__(8) unsigned long long mbar;

    const int tid   = threadIdx.x;
    const int q     = tid & 3;            // gate: 0=i,1=f,2=g,3=o
    const int jloc  = tid >> 2;           // 0..63
    const uint32_t rank = ctarank();
    const int batch = blockIdx.x >> 1;
    const int jglob = (int)rank * 64 + jloc;
    const int grow  = q * H_ + jglob;     // gate row in [0,512)

    // ---- register-resident weights, split by column half ----
    unsigned long long wl[32], wr[32];
    {
        const float* row = W_hh + (size_t)grow * H_;
        const ulonglong2* pl = reinterpret_cast<const ulonglong2*>(row + (int)rank * 64);
        const ulonglong2* pr = reinterpret_cast<const ulonglong2*>(row + (int)(rank ^ 1u) * 64);
        #pragma unroll
        for (int i = 0; i < 16; i++) { ulonglong2 v = pl[i]; wl[2*i] = v.x; wl[2*i+1] = v.y; }
        #pragma unroll
        for (int i = 0; i < 16; i++) { ulonglong2 v = pr[i]; wr[2*i] = v.x; wr[2*i+1] = v.y; }
    }
    const float wih  = W_ih[grow];
    const float bias = b_ih[grow] + b_hh[grow];
    // sigmoid(x) = 0.5*tanh(0.5x)+0.5 ; tanh(x) = tanh(x)
    const float sA = (q == 2) ? 1.f : 0.5f;
    const float sB = (q == 2) ? 1.f : 0.5f;
    const float sC = (q == 2) ? 0.f : 0.5f;

    float c = c0[batch * H_ + jglob];     // replicated across 4 lanes of a group

    if (tid < H_) hbuf[0][tid] = h0[batch * H_ + tid];
    for (int i = tid; i < T_; i += NT) xs[i] = data[(size_t)batch * T_ + i];

    const uint32_t mbar_a  = smem_u32(&mbar);
    const uint32_t hb_a    = smem_u32(&hbuf[0][0]);
    const uint32_t peer    = rank ^ 1u;
    const uint32_t peer_hb = mapa_u32(hb_a, peer);
    const uint32_t peer_mb = mapa_u32(mbar_a, peer);

    const int locOff = (int)rank * 64;
    const int remOff = (int)peer * 64;
    const uint32_t src_loc0 = hb_a    + (uint32_t)locOff * 4u;              // hbuf[0][locOff]
    const uint32_t dst_loc0 = peer_hb + (uint32_t)locOff * 4u;              // peer hbuf[0][locOff]

    if (tid == 0) {
        asm volatile("mbarrier.init.shared.b64 [%0], %1;" :: "r"(mbar_a), "r"(1u) : "memory");
        asm volatile("mbarrier.arrive.shared.b64 _, [%0];" :: "r"(mbar_a) : "memory");  // complete phase 0
    }
    __syncthreads();
    asm volatile("barrier.cluster.arrive.aligned;" ::: "memory");
    asm volatile("barrier.cluster.wait.aligned;"   ::: "memory");

    const int lane = tid & 31;
    const int b4   = lane & ~3;

    // prologue: local-half partial dot over hbuf[0]
    unsigned long long a0 = 0ull, a1 = 0ull, a2 = 0ull, a3 = 0ull;
    {
        const ulonglong2* hp = reinterpret_cast<const ulonglong2*>(&hbuf[0][locOff]);
        DOT_HALF(wl, hp)
    }

    #pragma unroll 1
    for (int t = 0; t < T_; ++t) {
        const int p  = t & 1;
        const int w2 = p ^ 1;
        const float bx = fmaf(wih, xs[t], bias);   // before the wait

        // phase t: remote half of hbuf[p] has arrived
        MBAR_WAIT(mbar_a, (uint32_t)p);
        if (tid == 0) {                            // register next phase's 256 bytes
            asm volatile("mbarrier.arrive.expect_tx.shared::cta.b64 _, [%0], %1;"
                         :: "r"(mbar_a), "r"(256u) : "memory");
        }

        // finish the dot with the remote half
        {
            const ulonglong2* hp = reinterpret_cast<const ulonglong2*>(&hbuf[p][remOff]);
            DOT_HALF(wr, hp)
        }
        float s;
        {
            unsigned long long s01, s23, st;
            asm("add.rn.f32x2 %0, %1, %2;" : "=l"(s01) : "l"(a0),  "l"(a1));
            asm("add.rn.f32x2 %0, %1, %2;" : "=l"(s23) : "l"(a2),  "l"(a3));
            asm("add.rn.f32x2 %0, %1, %2;" : "=l"(st)  : "l"(s01), "l"(s23));
            float lo, hi;
            asm("mov.b64 {%0,%1}, %2;" : "=f"(lo), "=f"(hi) : "l"(st));
            s = lo + hi;
        }

        const float pre = s + bx;
        const float act = fmaf(tanh_fast(pre * sA), sB, sC);

        // gather the 4 gates of this hidden unit (adjacent lanes)
        float gi = __shfl_sync(0xffffffffu, act, b4);
        float gf = __shfl_sync(0xffffffffu, act, b4 | 1);
        float gg = __shfl_sync(0xffffffffu, act, b4 | 2);
        float go = __shfl_sync(0xffffffffu, act, b4 | 3);

        c = fmaf(gf, c, gi * gg);
        const float hn = go * tanh_fast(c);

        if (q == 0) hbuf[w2][jglob] = hn;          // stage local half (also the local copy)
        __syncthreads();                            // local half visible CTA-wide

        if (tid == 0) {
            // make generic STS visible to the async proxy, then ONE bulk copy
            // of the 256B local half to the peer with a single tx update.
            asm volatile("fence.proxy.async.shared::cta;" ::: "memory");
            asm volatile(
                "cp.async.bulk.shared::cluster.shared::cta.mbarrier::complete_tx::bytes "
                "[%0], [%1], 256, [%2];"
                :: "r"(dst_loc0 + (uint32_t)(w2 * H_) * 4u),
                   "r"(src_loc0 + (uint32_t)(w2 * H_) * 4u),
                   "r"(peer_mb) : "memory");
        }

        // local-half partial dot for the NEXT step (overlaps the DSMEM flight)
        a0 = a1 = a2 = a3 = 0ull;
        {
            const ulonglong2* hp = reinterpret_cast<const ulonglong2*>(&hbuf[w2][locOff]);
            DOT_HALF(wl, hp)
        }
    }

    // phase T_ (parity 0): remote half of hbuf[0] (final h) has arrived
    MBAR_WAIT(mbar_a, 0u);

    if (rank == 0 && tid < 32) {
        float s = 0.f;
        #pragma unroll
        for (int m = 0; m < 4; m++)
            s = fmaf(hbuf[0][tid * 4 + m], W_out[tid * 4 + m], s);
        #pragma unroll
        for (int off = 16; off; off >>= 1)
            s += __shfl_xor_sync(0xffffffffu, s, off);
        if (tid == 0) out[batch] = s + b_out[0];
    }

    // no CTA exits while its peer may still write this CTA's smem
    asm volatile("barrier.cluster.arrive.aligned;" ::: "memory");
    asm volatile("barrier.cluster.wait.aligned;"   ::: "memory");
}

extern "C" void kernel_launch(void* const* d_in, const int* in_sizes, int n_in,
                              void* d_out, int out_size)
{
    const float* data  = (const float*)d_in[0];
    const float* h0    = (const float*)d_in[1];
    const float* c0    = (const float*)d_in[2];
    const float* W_ih  = (const float*)d_in[3];
    const float* W_hh  = (const float*)d_in[4];
    const float* b_ih  = (const float*)d_in[5];
    const float* b_hh  = (const float*)d_in[6];
    const float* W_out = (const float*)d_in[7];
    const float* b_out = (const float*)d_in[8];
    float* out = (float*)d_out;

    lstm_kernel<<<B_ * 2, NT>>>(data, h0, c0, W_ih, W_hh, b_ih, b_hh, W_out, b_out, out);
}

// round 5
// speedup vs baseline: 1.4952x; 1.4952x over previous
#include <cuda_runtime.h>
#include <cstdint>

// LSTM: B=64, T=4096, H=128, gates i,f,g,o; Linear(H->1) on h_T.
// 64 clusters x 2 CTAs (128 CTAs, 1/SM). Each CTA owns hidden [rank*64, rank*64+64).
// Thread map: q = tid&3 (gate), jloc = tid>>2. 256 gate rows/CTA, weights fully
// register-resident as f32x2 pairs split into local/remote column halves.
// Per step: local-half dot overlaps the peer DSMEM flight; remote h arrives via
// 32x st.async.b64 (packed pairs) + mbarrier complete_tx (256B/phase);
// cta-scope acquire on the wait; MUFU.TANH activations; bias+W_ih*x folded into
// the accumulator init; one __syncthreads per step.

#define B_ 64
#define T_ 4096
#define H_ 128
#define NT 256

__device__ __forceinline__ uint32_t smem_u32(const void* p) {
    uint32_t a;
    asm("{ .reg .u64 t; cvta.to.shared.u64 t, %1; cvt.u32.u64 %0, t; }" : "=r"(a) : "l"(p));
    return a;
}
__device__ __forceinline__ uint32_t ctarank() {
    uint32_t r; asm("mov.u32 %0, %%cluster_ctarank;" : "=r"(r)); return r;
}
__device__ __forceinline__ uint32_t mapa_u32(uint32_t a, uint32_t rk) {
    uint32_t r; asm("mapa.shared::cluster.u32 %0, %1, %2;" : "=r"(r) : "r"(a), "r"(rk)); return r;
}
__device__ __forceinline__ float tanh_fast(float x) {
    float y; asm("tanh.approx.f32 %0, %1;" : "=f"(y) : "f"(x)); return y;
}

// 32 packed FMAs (64 floats) of one column-half: W[32] f32x2 pairs vs 16 LDS.128 of h.
#define DOT_HALF(Wp, HP)                                                              \
    _Pragma("unroll")                                                                 \
    for (int i_ = 0; i_ < 8; i_++) {                                                  \
        ulonglong2 h2_ = (HP)[2*i_], h3_ = (HP)[2*i_ + 1];                            \
        asm("fma.rn.f32x2 %0, %1, %2, %0;" : "+l"(a0) : "l"((Wp)[4*i_    ]), "l"(h2_.x)); \
        asm("fma.rn.f32x2 %0, %1, %2, %0;" : "+l"(a1) : "l"((Wp)[4*i_ + 1]), "l"(h2_.y)); \
        asm("fma.rn.f32x2 %0, %1, %2, %0;" : "+l"(a2) : "l"((Wp)[4*i_ + 2]), "l"(h3_.x)); \
        asm("fma.rn.f32x2 %0, %1, %2, %0;" : "+l"(a3) : "l"((Wp)[4*i_ + 3]), "l"(h3_.y)); \
    }

// cta-scope acquire: async-proxy data delivered with complete_tx into LOCAL smem.
#define MBAR_WAIT(addr, par)                                                          \
    asm volatile(                                                                     \
        "{\n\t"                                                                       \
        ".reg .pred P1;\n\t"                                                          \
        "WL_%=:\n\t"                                                                  \
        "mbarrier.try_wait.parity.acquire.cta.shared::cta.b64 P1, [%0], %1, 0x989680;\n\t" \
        "@P1 bra.uni WD_%=;\n\t"                                                      \
        "bra.uni WL_%=;\n\t"                                                          \
        "WD_%=:\n\t"                                                                  \
        "}" :: "r"(addr), "r"(par) : "memory")

__global__ void __launch_bounds__(NT, 1) __cluster_dims__(2, 1, 1)
lstm_kernel(const float* __restrict__ data, const float* __restrict__ h0,
            const float* __restrict__ c0,   const float* __restrict__ W_ih,
            const float* __restrict__ W_hh, const float* __restrict__ b_ih,
            const float* __restrict__ b_hh, const float* __restrict__ W_out,
            const float* __restrict__ b_out, float* __restrict__ out)
{
    __shared__ __align__(16) float hbuf[2][H_];   // double-buffered full hidden state
    __shared__ __align__(16) float xs[T_];        // whole input sequence for this batch
    __shared__ __align__(8) unsigned long long mbar;

    const int tid   = threadIdx.x;
    const int q     = tid & 3;            // gate: 0=i,1=f,2=g,3=o
    const int jloc  = tid >> 2;           // 0..63
    const uint32_t rank = ctarank();
    const int batch = blockIdx.x >> 1;
    const int jglob = (int)rank * 64 + jloc;
    const int grow  = q * H_ + jglob;     // gate row in [0,512)

    // ---- register-resident weights, split by column half ----
    unsigned long long wl[32], wr[32];
    {
        const float* row = W_hh + (size_t)grow * H_;
        const ulonglong2* pl = reinterpret_cast<const ulonglong2*>(row + (int)rank * 64);
        const ulonglong2* pr = reinterpret_cast<const ulonglong2*>(row + (int)(rank ^ 1u) * 64);
        #pragma unroll
        for (int i = 0; i < 16; i++) { ulonglong2 v = pl[i]; wl[2*i] = v.x; wl[2*i+1] = v.y; }
        #pragma unroll
        for (int i = 0; i < 16; i++) { ulonglong2 v = pr[i]; wr[2*i] = v.x; wr[2*i+1] = v.y; }
    }
    const float wih  = W_ih[grow];
    const float bias = b_ih[grow] + b_hh[grow];
    // sigmoid(x) = 0.5*tanh(0.5x)+0.5 ; tanh(x) = tanh(x)
    const float sA = (q == 2) ? 1.f : 0.5f;
    const float sB = (q == 2) ? 1.f : 0.5f;
    const float sC = (q == 2) ? 0.f : 0.5f;

    float c = c0[batch * H_ + jglob];     // replicated across 4 lanes of a group

    if (tid < H_) hbuf[0][tid] = h0[batch * H_ + tid];
    for (int i = tid; i < T_; i += NT) xs[i] = data[(size_t)batch * T_ + i];

    const uint32_t mbar_a  = smem_u32(&mbar);
    const uint32_t hb_a    = smem_u32(&hbuf[0][0]);
    const uint32_t peer    = rank ^ 1u;
    const uint32_t peer_hb = mapa_u32(hb_a, peer);
    const uint32_t peer_mb = mapa_u32(mbar_a, peer);

    if (tid == 0) {
        asm volatile("mbarrier.init.shared.b64 [%0], %1;" :: "r"(mbar_a), "r"(1u) : "memory");
        asm volatile("mbarrier.arrive.shared.b64 _, [%0];" :: "r"(mbar_a) : "memory");  // complete phase 0
    }
    __syncthreads();
    asm volatile("barrier.cluster.arrive.aligned;" ::: "memory");
    asm volatile("barrier.cluster.wait.aligned;"   ::: "memory");

    const int locOff = (int)rank * 64;
    const int remOff = (int)peer * 64;
    const int lane   = tid & 31;
    const int b4     = lane & ~3;
    const bool sender = ((tid & 7) == 0);   // q==0 && even jloc  -> 32 senders
    const uint32_t send_base = peer_hb + (uint32_t)jglob * 4u;  // + w2*H_*4 per step

    // prologue: a0 seeded with bx(t=0); local-half partial dot over hbuf[0]
    unsigned long long a0, a1 = 0ull, a2 = 0ull, a3 = 0ull;
    {
        float bx0 = fmaf(wih, xs[0], bias);
        asm("mov.b64 %0, {%1, %2};" : "=l"(a0) : "f"(bx0), "f"(0.f));
        const ulonglong2* hp = reinterpret_cast<const ulonglong2*>(&hbuf[0][locOff]);
        DOT_HALF(wl, hp)
    }

    #pragma unroll 1
    for (int t = 0; t < T_; ++t) {
        const int p  = t & 1;
        const int w2 = p ^ 1;

        // phase t: remote half of hbuf[p] has arrived
        MBAR_WAIT(mbar_a, (uint32_t)p);
        if (tid == 0) {                            // register next phase's 256 bytes
            asm volatile("mbarrier.arrive.expect_tx.shared::cta.b64 _, [%0], %1;"
                         :: "r"(mbar_a), "r"(256u) : "memory");
        }

        // finish the dot with the remote half
        {
            const ulonglong2* hp = reinterpret_cast<const ulonglong2*>(&hbuf[p][remOff]);
            DOT_HALF(wr, hp)
        }
        float s;   // includes bx (seeded in a0)
        {
            unsigned long long s01, s23, st;
            asm("add.rn.f32x2 %0, %1, %2;" : "=l"(s01) : "l"(a0),  "l"(a1));
            asm("add.rn.f32x2 %0, %1, %2;" : "=l"(s23) : "l"(a2),  "l"(a3));
            asm("add.rn.f32x2 %0, %1, %2;" : "=l"(st)  : "l"(s01), "l"(s23));
            float lo, hi;
            asm("mov.b64 {%0,%1}, %2;" : "=f"(lo), "=f"(hi) : "l"(st));
            s = lo + hi;
        }

        const float act = fmaf(tanh_fast(s * sA), sB, sC);

        // gather the 4 gates of this hidden unit (adjacent lanes)
        float gi = __shfl_sync(0xffffffffu, act, b4);
        float gf = __shfl_sync(0xffffffffu, act, b4 | 1);
        float gg = __shfl_sync(0xffffffffu, act, b4 | 2);
        float go = __shfl_sync(0xffffffffu, act, b4 | 3);

        c = fmaf(gf, c, gi * gg);
        const float hn = go * tanh_fast(c);

        // pack (hn_j, hn_{j+1}) and send as one b64: 32 senders, 32 tx updates
        const float hn2 = __shfl_down_sync(0xffffffffu, hn, 4);
        if (sender) {
            unsigned long long pk;
            asm("mov.b64 %0, {%1, %2};" : "=l"(pk) : "f"(hn), "f"(hn2));
            asm volatile(
                "st.async.shared::cluster.mbarrier::complete_tx::bytes.b64 [%0], %1, [%2];"
                :: "r"(send_base + (uint32_t)(w2 * H_) * 4u), "l"(pk), "r"(peer_mb)
                : "memory");
        }
        if (q == 0) hbuf[w2][jglob] = hn;          // local copy
        __syncthreads();                            // local half visible CTA-wide

        // seed a0 with bx(t+1); local-half partial dot for the NEXT step
        {
            const int tn = (t + 1 < T_) ? (t + 1) : 0;
            float bxn = fmaf(wih, xs[tn], bias);
            asm("mov.b64 %0, {%1, %2};" : "=l"(a0) : "f"(bxn), "f"(0.f));
            a1 = a2 = a3 = 0ull;
            const ulonglong2* hp = reinterpret_cast<const ulonglong2*>(&hbuf[w2][locOff]);
            DOT_HALF(wl, hp)
        }
    }

    // phase T_ (parity 0): remote half of hbuf[0] (final h) has arrived
    MBAR_WAIT(mbar_a, 0u);

    if (rank == 0 && tid < 32) {
        float s = 0.f;
        #pragma unroll
        for (int m = 0; m < 4; m++)
            s = fmaf(hbuf[0][tid * 4 + m], W_out[tid * 4 + m], s);
        #pragma unroll
        for (int off = 16; off; off >>= 1)
            s += __shfl_xor_sync(0xffffffffu, s, off);
        if (tid == 0) out[batch] = s + b_out[0];
    }

    // no CTA exits while its peer may still write this CTA's smem
    asm volatile("barrier.cluster.arrive.aligned;" ::: "memory");
    asm volatile("barrier.cluster.wait.aligned;"   ::: "memory");
}

extern "C" void kernel_launch(void* const* d_in, const int* in_sizes, int n_in,
                              void* d_out, int out_size)
{
    const float* data  = (const float*)d_in[0];
    const float* h0    = (const float*)d_in[1];
    const float* c0    = (const float*)d_in[2];
    const float* W_ih  = (const float*)d_in[3];
    const float* W_hh  = (const float*)d_in[4];
    const float* b_ih  = (const float*)d_in[5];
    const float* b_hh  = (const float*)d_in[6];
    const float* W_out = (const float*)d_in[7];
    const float* b_out = (const float*)d_in[8];
    float* out = (float*)d_out;

    lstm_kernel<<<B_ * 2, NT>>>(data, h0, c0, W_ih, W_hh, b_ih, b_hh, W_out, b_out, out);
}

// round 6
// speedup vs baseline: 1.5003x; 1.0034x over previous
#include <cuda_runtime.h>
#include <cstdint>

// LSTM: B=64, T=4096, H=128, gates i,f,g,o; Linear(H->1) on h_T.
// 64 clusters x 2 CTAs (128 CTAs, 1/SM). Each CTA owns hidden [rank*64, rank*64+64).
// Lane map: q = tid&3 holds gate {0:i, 1:g, 2:f, 3:o} (remapped for butterfly
// combine), jloc = tid>>2. 256 gate rows/CTA, weights register-resident as f32x2
// pairs split into local/remote column halves. Per step: local-half dot overlaps
// the peer DSMEM flight; remote h via 64x st.async.b32 + complete_tx (256B/phase);
// cta-scope acquire wait; MUFU.TANH; bias+W_ih*x seeded into accumulator;
// c-update via 2x shfl_xor butterfly; one __syncthreads per step.

#define B_ 64
#define T_ 4096
#define H_ 128
#define NT 256

__device__ __forceinline__ uint32_t smem_u32(const void* p) {
    uint32_t a;
    asm("{ .reg .u64 t; cvta.to.shared.u64 t, %1; cvt.u32.u64 %0, t; }" : "=r"(a) : "l"(p));
    return a;
}
__device__ __forceinline__ uint32_t ctarank() {
    uint32_t r; asm("mov.u32 %0, %%cluster_ctarank;" : "=r"(r)); return r;
}
__device__ __forceinline__ uint32_t mapa_u32(uint32_t a, uint32_t rk) {
    uint32_t r; asm("mapa.shared::cluster.u32 %0, %1, %2;" : "=r"(r) : "r"(a), "r"(rk)); return r;
}
__device__ __forceinline__ float tanh_fast(float x) {
    float y; asm("tanh.approx.f32 %0, %1;" : "=f"(y) : "f"(x)); return y;
}

// 32 packed FMAs (64 floats) of one column-half: W[32] f32x2 pairs vs 16 LDS.128 of h.
#define DOT_HALF(Wp, HP)                                                              \
    _Pragma("unroll")                                                                 \
    for (int i_ = 0; i_ < 8; i_++) {                                                  \
        ulonglong2 h2_ = (HP)[2*i_], h3_ = (HP)[2*i_ + 1];                            \
        asm("fma.rn.f32x2 %0, %1, %2, %0;" : "+l"(a0) : "l"((Wp)[4*i_    ]), "l"(h2_.x)); \
        asm("fma.rn.f32x2 %0, %1, %2, %0;" : "+l"(a1) : "l"((Wp)[4*i_ + 1]), "l"(h2_.y)); \
        asm("fma.rn.f32x2 %0, %1, %2, %0;" : "+l"(a2) : "l"((Wp)[4*i_ + 2]), "l"(h3_.x)); \
        asm("fma.rn.f32x2 %0, %1, %2, %0;" : "+l"(a3) : "l"((Wp)[4*i_ + 3]), "l"(h3_.y)); \
    }

// cta-scope acquire: async-proxy data delivered with complete_tx into LOCAL smem.
#define MBAR_WAIT(addr, par)                                                          \
    asm volatile(                                                                     \
        "{\n\t"                                                                       \
        ".reg .pred P1;\n\t"                                                          \
        "WL_%=:\n\t"                                                                  \
        "mbarrier.try_wait.parity.acquire.cta.shared::cta.b64 P1, [%0], %1, 0x989680;\n\t" \
        "@P1 bra.uni WD_%=;\n\t"                                                      \
        "bra.uni WL_%=;\n\t"                                                          \
        "WD_%=:\n\t"                                                                  \
        "}" :: "r"(addr), "r"(par) : "memory")

__global__ void __launch_bounds__(NT, 1) __cluster_dims__(2, 1, 1)
lstm_kernel(const float* __restrict__ data, const float* __restrict__ h0,
            const float* __restrict__ c0,   const float* __restrict__ W_ih,
            const float* __restrict__ W_hh, const float* __restrict__ b_ih,
            const float* __restrict__ b_hh, const float* __restrict__ W_out,
            const float* __restrict__ b_out, float* __restrict__ out)
{
    __shared__ __align__(16) float hbuf[2][H_];   // double-buffered full hidden state
    __shared__ __align__(16) float xs[T_];        // whole input sequence for this batch
    __shared__ __align__(8) unsigned long long mbar;

    const int tid   = threadIdx.x;
    const int q     = tid & 3;            // lane gate: 0=i, 1=g, 2=f, 3=o
    const int jloc  = tid >> 2;           // 0..63
    const uint32_t rank = ctarank();
    const int batch = blockIdx.x >> 1;
    const int jglob = (int)rank * 64 + jloc;
    // PyTorch row blocks: i=0,f=1,g=2,o=3 ; lane order i,g,f,o -> base {0,2,1,3}
    const int gbase = (q == 0) ? 0 : (q == 1) ? 2 : (q == 2) ? 1 : 3;
    const int grow  = gbase * H_ + jglob; // gate row in [0,512)

    // ---- register-resident weights, split by column half ----
    unsigned long long wl[32], wr[32];
    {
        const float* row = W_hh + (size_t)grow * H_;
        const ulonglong2* pl = reinterpret_cast<const ulonglong2*>(row + (int)rank * 64);
        const ulonglong2* pr = reinterpret_cast<const ulonglong2*>(row + (int)(rank ^ 1u) * 64);
        #pragma unroll
        for (int i = 0; i < 16; i++) { ulonglong2 v = pl[i]; wl[2*i] = v.x; wl[2*i+1] = v.y; }
        #pragma unroll
        for (int i = 0; i < 16; i++) { ulonglong2 v = pr[i]; wr[2*i] = v.x; wr[2*i+1] = v.y; }
    }
    const float wih  = W_ih[grow];
    const float bias = b_ih[grow] + b_hh[grow];
    // sigmoid(x) = 0.5*tanh(0.5x)+0.5 ; tanh for gate g (lane q==1)
    const float sA = (q == 1) ? 1.f : 0.5f;
    const float sB = (q == 1) ? 1.f : 0.5f;
    const float sC = (q == 1) ? 0.f : 0.5f;

    float c = c0[batch * H_ + jglob];     // identical across the 4 lanes of a unit

    if (tid < H_) hbuf[0][tid] = h0[batch * H_ + tid];
    for (int i = tid; i < T_; i += NT) xs[i] = data[(size_t)batch * T_ + i];

    const uint32_t mbar_a  = smem_u32(&mbar);
    const uint32_t hb_a    = smem_u32(&hbuf[0][0]);
    const uint32_t peer    = rank ^ 1u;
    const uint32_t peer_hb = mapa_u32(hb_a, peer);
    const uint32_t peer_mb = mapa_u32(mbar_a, peer);

    if (tid == 0) {
        asm volatile("mbarrier.init.shared.b64 [%0], %1;" :: "r"(mbar_a), "r"(1u) : "memory");
        asm volatile("mbarrier.arrive.shared.b64 _, [%0];" :: "r"(mbar_a) : "memory");  // complete phase 0
    }
    __syncthreads();
    asm volatile("barrier.cluster.arrive.aligned;" ::: "memory");
    asm volatile("barrier.cluster.wait.aligned;"   ::: "memory");

    const int locOff = (int)rank * 64;
    const int remOff = (int)peer * 64;
    const bool sender = (q == 2);                                  // 64 senders
    const uint32_t send_base = peer_hb + (uint32_t)jglob * 4u;     // + w2*H_*4 per step

    // prologue: a0 seeded with bx(t=0); local-half partial dot over hbuf[0]
    unsigned long long a0, a1 = 0ull, a2 = 0ull, a3 = 0ull;
    {
        float bx0 = fmaf(wih, xs[0], bias);
        asm("mov.b64 %0, {%1, %2};" : "=l"(a0) : "f"(bx0), "f"(0.f));
        const ulonglong2* hp = reinterpret_cast<const ulonglong2*>(&hbuf[0][locOff]);
        DOT_HALF(wl, hp)
    }

    #pragma unroll 1
    for (int t = 0; t < T_; ++t) {
        const int p  = t & 1;
        const int w2 = p ^ 1;

        // phase t: remote half of hbuf[p] has arrived
        MBAR_WAIT(mbar_a, (uint32_t)p);
        if (tid == 0) {                            // register next phase's 256 bytes
            asm volatile("mbarrier.arrive.expect_tx.shared::cta.b64 _, [%0], %1;"
                         :: "r"(mbar_a), "r"(256u) : "memory");
        }

        // finish the dot with the remote half
        {
            const ulonglong2* hp = reinterpret_cast<const ulonglong2*>(&hbuf[p][remOff]);
            DOT_HALF(wr, hp)
        }
        float s;   // includes bx (seeded in a0)
        {
            unsigned long long s01, s23, st;
            asm("add.rn.f32x2 %0, %1, %2;" : "=l"(s01) : "l"(a0),  "l"(a1));
            asm("add.rn.f32x2 %0, %1, %2;" : "=l"(s23) : "l"(a2),  "l"(a3));
            asm("add.rn.f32x2 %0, %1, %2;" : "=l"(st)  : "l"(s01), "l"(s23));
            float lo, hi;
            asm("mov.b64 {%0,%1}, %2;" : "=f"(lo), "=f"(hi) : "l"(st));
            s = lo + hi;
        }

        const float act = fmaf(tanh_fast(s * sA), sB, sC);

        // butterfly combine: lanes hold {i, g, f, o}
        // xor1: q0<-g, q1<-i, q2<-o, q3<-f
        const float s1 = __shfl_xor_sync(0xffffffffu, act, 1);
        // q0: i*g, q1: g*i, q2: f*c (own f), q3: f*c (recv f)
        const float pprod = (q < 2) ? (act * s1) : ((q == 2) ? (act * c) : (s1 * c));
        // xor2: pairs (q0,q2) and (q1,q3) exchange -> c_new everywhere
        const float s2 = __shfl_xor_sync(0xffffffffu, pprod, 2);
        c = pprod + s2;                                    // i*g + f*c, all lanes

        // o available at q2 (via s1) and q3 (own); q2 stages + sends
        const float og = (q == 2) ? s1 : act;              // valid for q>=2
        const float hn = og * tanh_fast(c);

        if (sender) {
            hbuf[w2][jglob] = hn;                          // local copy
            asm volatile(
                "st.async.shared::cluster.mbarrier::complete_tx::bytes.b32 [%0], %1, [%2];"
                :: "r"(send_base + (uint32_t)(w2 * H_) * 4u), "r"(__float_as_uint(hn)),
                   "r"(peer_mb) : "memory");
        }
        __syncthreads();                                   // local half visible CTA-wide

        // seed a0 with bx(t+1); local-half partial dot for the NEXT step
        {
            const int tn = (t + 1 < T_) ? (t + 1) : 0;
            float bxn = fmaf(wih, xs[tn], bias);
            asm("mov.b64 %0, {%1, %2};" : "=l"(a0) : "f"(bxn), "f"(0.f));
            a1 = a2 = a3 = 0ull;
            const ulonglong2* hp = reinterpret_cast<const ulonglong2*>(&hbuf[w2][locOff]);
            DOT_HALF(wl, hp)
        }
    }

    // phase T_ (parity 0): remote half of hbuf[0] (final h) has arrived
    MBAR_WAIT(mbar_a, 0u);

    if (rank == 0 && tid < 32) {
        float s = 0.f;
        #pragma unroll
        for (int m = 0; m < 4; m++)
            s = fmaf(hbuf[0][tid * 4 + m], W_out[tid * 4 + m], s);
        #pragma unroll
        for (int off = 16; off; off >>= 1)
            s += __shfl_xor_sync(0xffffffffu, s, off);
        if (tid == 0) out[batch] = s + b_out[0];
    }

    // no CTA exits while its peer may still write this CTA's smem
    asm volatile("barrier.cluster.arrive.aligned;" ::: "memory");
    asm volatile("barrier.cluster.wait.aligned;"   ::: "memory");
}

extern "C" void kernel_launch(void* const* d_in, const int* in_sizes, int n_in,
                              void* d_out, int out_size)
{
    const float* data  = (const float*)d_in[0];
    const float* h0    = (const float*)d_in[1];
    const float* c0    = (const float*)d_in[2];
    const float* W_ih  = (const float*)d_in[3];
    const float* W_hh  = (const float*)d_in[4];
    const float* b_ih  = (const float*)d_in[5];
    const float* b_hh  = (const float*)d_in[6];
    const float* W_out = (const float*)d_in[7];
    const float* b_out = (const float*)d_in[8];
    float* out = (float*)d_out;

    lstm_kernel<<<B_ * 2, NT>>>(data, h0, c0, W_ih, W_hh, b_ih, b_hh, W_out, b_out, out);
}